// round 7
// baseline (speedup 1.0000x reference)
#include <cuda_runtime.h>
#include <cuda_bf16.h>
#include <math.h>
#include <float.h>
#include <stdint.h>

// ---------------------------------------------------------------------------
// Problem constants
// ---------------------------------------------------------------------------
#define NN      100000
#define EE_MAX  1700000          // E + N upper bound for scratch sizing
#define DIMD    128
#define OUTD    64
#define NLAYER  3
#define NEG_SLOPE 0.2f
#define RES_W     0.5f
#define SCAN_CHUNK 1024

// ---------------------------------------------------------------------------
// Device scratch
// ---------------------------------------------------------------------------
__device__ __align__(16) float g_x0   [NN * DIMD];
__device__ __align__(16) float g_xcur [NN * DIMD];
__device__ __align__(16) float g_h    [NN * DIMD];
__device__ __align__(16) float g_c    [NN * DIMD];
__device__ __align__(16) float g_xp   [NN * DIMD];
__device__ __align__(16) float g_htmp [NN * DIMD];
__device__ __align__(16) float g_gates[NN * 4 * DIMD];
__device__ __align__(16) float g_asrc [NN];
__device__ __align__(16) float g_adst [NN];
__device__ __align__(16) float g_wt   [DIMD * DIMD];
__device__ __align__(16) float g_wcat [4 * DIMD * 3 * DIMD];
// CSR scratch
__device__ __align__(16) int   g_deg  [NN];
__device__ __align__(16) int   g_epos [NN];
__device__ __align__(16) int   g_off  [NN + 1];
__device__ __align__(16) int   g_bsum [128];
__device__ __align__(16) int   g_boff [128];
__device__ __align__(16) int   g_esrc [EE_MAX];

// ---------------------------------------------------------------------------
// PTX helpers (sm_80+ ISA only — harness targets plain sm_100, no tcgen05)
// ---------------------------------------------------------------------------
__device__ __forceinline__ uint32_t smem_u32(const void* p) {
    uint32_t a;
    asm("{ .reg .u64 t; cvta.to.shared.u64 t, %1; cvt.u32.u64 %0, t; }"
        : "=r"(a) : "l"(p));
    return a;
}

__device__ __forceinline__ void cp16(uint32_t s, const void* g, bool pred) {
    int sz = pred ? 16 : 0;
    asm volatile("cp.async.cg.shared.global [%0], [%1], 16, %2;"
                 :: "r"(s), "l"(g), "r"(sz));
}
__device__ __forceinline__ void cp_commit() {
    asm volatile("cp.async.commit_group;" ::: "memory");
}
template <int N>
__device__ __forceinline__ void cp_wait() {
    asm volatile("cp.async.wait_group %0;" :: "n"(N) : "memory");
}

__device__ __forceinline__ void ldmx4(uint32_t* r, uint32_t addr) {
    asm volatile("ldmatrix.sync.aligned.m8n8.x4.shared.b16 {%0,%1,%2,%3}, [%4];"
                 : "=r"(r[0]), "=r"(r[1]), "=r"(r[2]), "=r"(r[3]) : "r"(addr));
}
__device__ __forceinline__ void mma1688(float* d, const uint32_t* a, const uint32_t* b) {
    asm volatile(
        "mma.sync.aligned.m16n8k8.row.col.f32.tf32.tf32.f32 "
        "{%0,%1,%2,%3}, {%4,%5,%6,%7}, {%8,%9}, {%0,%1,%2,%3};"
        : "+f"(d[0]), "+f"(d[1]), "+f"(d[2]), "+f"(d[3])
        : "r"(a[0]), "r"(a[1]), "r"(a[2]), "r"(a[3]), "r"(b[0]), "r"(b[1]));
}

// ---------------------------------------------------------------------------
// tf32 mma.sync GEMM (truncation fast-path: no cvt in the hot loop).
// C[M,Nc] = concat_K(A0|A1|A2)[M,K] @ B[Nc,K]^T (+bias)
// ---------------------------------------------------------------------------
template <int BN>
__global__ __launch_bounds__(256)
void gemm_mma(const float* __restrict__ a0, const float* __restrict__ a1,
              const float* __restrict__ a2, const float* __restrict__ Bm,
              const float* __restrict__ bias, float* __restrict__ C,
              int M, int Nc, int K)
{
    constexpr int BM = 128, BK = 32, LDA = BK + 4;   // 36 floats/row
    constexpr int NTW = BN / 16;
    constexpr int STAGEF = (BM + BN) * LDA;
    extern __shared__ float smem[];

    const int tid  = threadIdx.x;
    const int wid  = tid >> 5;
    const int lane = tid & 31;
    const int wm   = wid & 3;
    const int wn   = wid >> 2;
    const int rowBase = blockIdx.y * BM;
    const int colBase = blockIdx.x * BN;
    const float* aparts[3] = {a0, a1, a2};

    float acc[2][NTW][4];
#pragma unroll
    for (int mt = 0; mt < 2; mt++)
#pragma unroll
        for (int nt = 0; nt < NTW; nt++)
#pragma unroll
            for (int q = 0; q < 4; q++) acc[mt][nt][q] = 0.f;

    const int NCH = K >> 5;

    auto load_chunk = [&](int ck) {
        float* as = smem + (ck & 1) * STAGEF;
        float* bs = as + BM * LDA;
        const float* Ap = aparts[ck >> 2];
        const int kA = (ck & 3) * 32;
        const int k0 = ck * 32;
        for (int i = tid; i < BM * 8; i += 256) {
            int r = i >> 3, c = i & 7;
            int grow = rowBase + r;
            bool ok = grow < M;
            int srow = ok ? grow : (M - 1);   // clamp: address always in-bounds
            cp16(smem_u32(as + r * LDA + c * 4),
                 Ap + (size_t)srow * 128 + kA + c * 4, ok);
        }
        for (int i = tid; i < BN * 8; i += 256) {
            int r = i >> 3, c = i & 7;
            cp16(smem_u32(bs + r * LDA + c * 4),
                 Bm + (size_t)(colBase + r) * K + k0 + c * 4, true);
        }
        cp_commit();
    };

    load_chunk(0);
    for (int ck = 0; ck < NCH; ck++) {
        if (ck + 1 < NCH) { load_chunk(ck + 1); cp_wait<1>(); }
        else              { cp_wait<0>(); }
        __syncthreads();

        const float* as = smem + (ck & 1) * STAGEF;
        const float* bs = as + BM * LDA;
        uint32_t aAddr = smem_u32(as) +
            (uint32_t)(((wm * 32 + (lane & 15)) * LDA + ((lane >> 4) << 2)) * 4);
        uint32_t bAddr = smem_u32(bs) +
            (uint32_t)(((wn * (BN / 2) + (lane & 7) + ((lane >> 4) << 3)) * LDA
                        + (((lane >> 3) & 1) << 2)) * 4);

#pragma unroll
        for (int ks = 0; ks < 4; ks++) {
            uint32_t af[2][4];
#pragma unroll
            for (int mt = 0; mt < 2; mt++)
                ldmx4(af[mt], aAddr + (uint32_t)(mt * 16 * LDA * 4 + ks * 32));
            uint32_t bf[NTW][2];
#pragma unroll
            for (int p = 0; p < NTW / 2; p++) {
                uint32_t t[4];
                ldmx4(t, bAddr + (uint32_t)(p * 16 * LDA * 4 + ks * 32));
                bf[2 * p][0]     = t[0];
                bf[2 * p][1]     = t[1];
                bf[2 * p + 1][0] = t[2];
                bf[2 * p + 1][1] = t[3];
            }
#pragma unroll
            for (int mt = 0; mt < 2; mt++)
#pragma unroll
                for (int nt = 0; nt < NTW; nt++)
                    mma1688(acc[mt][nt], af[mt], bf[nt]);
        }
        __syncthreads();
    }

    // epilogue
#pragma unroll
    for (int mt = 0; mt < 2; mt++) {
        int r0 = rowBase + wm * 32 + mt * 16 + (lane >> 2);
#pragma unroll
        for (int nt = 0; nt < NTW; nt++) {
            int col = colBase + wn * (BN / 2) + nt * 8 + (lane & 3) * 2;
            float b0 = 0.f, b1 = 0.f;
            if (bias) { b0 = bias[col]; b1 = bias[col + 1]; }
            if (r0 < M) {
                float2 v = make_float2(acc[mt][nt][0] + b0, acc[mt][nt][1] + b1);
                *(float2*)(C + (size_t)r0 * Nc + col) = v;
            }
            if (r0 + 8 < M) {
                float2 v = make_float2(acc[mt][nt][2] + b0, acc[mt][nt][3] + b1);
                *(float2*)(C + (size_t)(r0 + 8) * Nc + col) = v;
            }
        }
    }
}

// ---------------------------------------------------------------------------
// CSR build (per launch; edges constant across layers)
// ---------------------------------------------------------------------------
__global__ void csr_zero_kernel(int n)
{
    int i = blockIdx.x * blockDim.x + threadIdx.x;
    if (i < n) { g_deg[i] = 0; g_epos[i] = 0; }
}

__global__ void csr_count_kernel(const int* __restrict__ dst, int E, int EP)
{
    int i = blockIdx.x * blockDim.x + threadIdx.x;
    if (i >= EP) return;
    int d = (i < E) ? dst[i] : (i - E);
    atomicAdd(&g_deg[d], 1);
}

// block-wise exclusive scan: each block handles SCAN_CHUNK elems (256 thr x4)
__global__ void scan_block_kernel(int n)
{
    __shared__ int sh[256];
    int t = threadIdx.x;
    int base = blockIdx.x * SCAN_CHUNK;
    int v[4]; int sum = 0;
#pragma unroll
    for (int j = 0; j < 4; j++) {
        int i = base + t * 4 + j;
        v[j] = (i < n) ? g_deg[i] : 0;
        sum += v[j];
    }
    sh[t] = sum;
    __syncthreads();
    // inclusive Hillis-Steele
    for (int off = 1; off < 256; off <<= 1) {
        int y = (t >= off) ? sh[t - off] : 0;
        __syncthreads();
        sh[t] += y;
        __syncthreads();
    }
    int excl = sh[t] - sum;
#pragma unroll
    for (int j = 0; j < 4; j++) {
        int i = base + t * 4 + j;
        if (i < n) g_off[i] = excl;
        excl += v[j];
    }
    if (t == 255) g_bsum[blockIdx.x] = sh[255];
}

__global__ void scan_bsum_kernel(int nb, int n)
{
    if (threadIdx.x == 0 && blockIdx.x == 0) {
        int run = 0;
        for (int b = 0; b < nb; b++) {
            int t = g_bsum[b];
            g_boff[b] = run;
            run += t;
        }
        g_off[n] = run;
    }
}

__global__ void scan_add_kernel(int n)
{
    int i = blockIdx.x * blockDim.x + threadIdx.x;
    if (i < n) g_off[i] += g_boff[i / SCAN_CHUNK];
}

__global__ void csr_scatter_kernel(const int* __restrict__ src,
                                   const int* __restrict__ dst, int E, int EP)
{
    int i = blockIdx.x * blockDim.x + threadIdx.x;
    if (i >= EP) return;
    int s = (i < E) ? src[i] : (i - E);
    int d = (i < E) ? dst[i] : (i - E);
    int pos = g_off[d] + atomicAdd(&g_epos[d], 1);
    g_esrc[pos] = s;
}

__global__ void csr_reset_epos_kernel(int n)
{
    int i = blockIdx.x * blockDim.x + threadIdx.x;
    if (i < n) g_epos[i] = 0;
}

// ---------------------------------------------------------------------------
// Elementwise / per-node kernels
// ---------------------------------------------------------------------------
__global__ void init_state_kernel(const float* __restrict__ x0, int count)
{
    int i = blockIdx.x * blockDim.x + threadIdx.x;
    if (i >= count) return;
    g_xcur[i] = x0[i];
    g_h[i] = 0.f;
    g_c[i] = 0.f;
}

__global__ void transpose_kernel(const float* __restrict__ W)
{
    int i = blockIdx.x * blockDim.x + threadIdx.x;
    if (i >= DIMD * DIMD) return;
    int r = i >> 7, c = i & 127;
    g_wt[r * DIMD + c] = W[c * DIMD + r];
}

__global__ void pack_wcat_kernel(const float* __restrict__ Wih,
                                 const float* __restrict__ Whh)
{
    int i = blockIdx.x * blockDim.x + threadIdx.x;
    if (i >= 4 * DIMD * 3 * DIMD) return;
    int r = i / (3 * DIMD);
    int c = i - r * (3 * DIMD);
    float v = (c < 2 * DIMD) ? Wih[r * 2 * DIMD + c]
                             : Whh[r * DIMD + (c - 2 * DIMD)];
    g_wcat[i] = v;
}

__global__ void alpha_kernel(const float4* __restrict__ as4,
                             const float4* __restrict__ ad4, int n)
{
    int gw   = (blockIdx.x * blockDim.x + threadIdx.x) >> 5;
    int lane = threadIdx.x & 31;
    if (gw >= n) return;
    float4 v  = ((const float4*)g_xp)[gw * 32 + lane];
    float4 s4 = as4[lane];
    float4 d4 = ad4[lane];
    float ds = v.x * s4.x + v.y * s4.y + v.z * s4.z + v.w * s4.w;
    float dd = v.x * d4.x + v.y * d4.y + v.z * d4.z + v.w * d4.w;
#pragma unroll
    for (int off = 16; off > 0; off >>= 1) {
        ds += __shfl_xor_sync(0xFFFFFFFFu, ds, off);
        dd += __shfl_xor_sync(0xFFFFFFFFu, dd, off);
    }
    if (lane == 0) { g_asrc[gw] = ds; g_adst[gw] = dd; }
}

__device__ __forceinline__ float leaky(float e)
{
    return e > 0.f ? e : NEG_SLOPE * e;
}

// Fused GAT aggregation: warp per dst node. Softmax over incoming edges,
// weighted gather of xp rows, bias + tanh, write htmp. No atomics.
__global__ void gat_gather_kernel(const float* __restrict__ gat_b, int n)
{
    int gw   = (blockIdx.x * blockDim.x + threadIdx.x) >> 5;
    int lane = threadIdx.x & 31;
    if (gw >= n) return;

    const int o0 = g_off[gw];
    const int o1 = g_off[gw + 1];
    const float ad = g_adst[gw];

    // pass A: segment max of leaky scores
    float m = -FLT_MAX;
    for (int e = o0 + lane; e < o1; e += 32) {
        int s = g_esrc[e];
        m = fmaxf(m, leaky(g_asrc[s] + ad));
    }
#pragma unroll
    for (int off = 16; off > 0; off >>= 1)
        m = fmaxf(m, __shfl_xor_sync(0xFFFFFFFFu, m, off));

    // pass B: exp weights + weighted row gather
    float4 acc = make_float4(0.f, 0.f, 0.f, 0.f);
    float den = 0.f;
    for (int b = o0; b < o1; b += 32) {
        int e = b + lane;
        int s = 0; float ex = 0.f;
        if (e < o1) {
            s = g_esrc[e];
            ex = expf(leaky(g_asrc[s] + ad) - m);
        }
        den += ex;
        int cnt = min(32, o1 - b);
        for (int j = 0; j < cnt; j++) {
            float exj = __shfl_sync(0xFFFFFFFFu, ex, j);
            int   sj  = __shfl_sync(0xFFFFFFFFu, s, j);
            float4 v = ((const float4*)g_xp)[sj * 32 + lane];
            acc.x += exj * v.x;
            acc.y += exj * v.y;
            acc.z += exj * v.z;
            acc.w += exj * v.w;
        }
    }
#pragma unroll
    for (int off = 16; off > 0; off >>= 1)
        den += __shfl_xor_sync(0xFFFFFFFFu, den, off);

    float inv = 1.f / (den + 1e-16f);
    float4 bv = ((const float4*)gat_b)[lane];
    float4 o;
    o.x = tanhf(acc.x * inv + bv.x);
    o.y = tanhf(acc.y * inv + bv.y);
    o.z = tanhf(acc.z * inv + bv.z);
    o.w = tanhf(acc.w * inv + bv.w);
    ((float4*)g_htmp)[gw * 32 + lane] = o;
}

__device__ __forceinline__ float sigmoidf_(float x)
{
    return 1.f / (1.f + expf(-x));
}

__global__ void lstm_kernel(int n)
{
    int i = blockIdx.x * blockDim.x + threadIdx.x;
    if (i >= n * DIMD) return;
    int node = i >> 7;
    int dd   = i & 127;
    const float* gr = g_gates + (size_t)node * 4 * DIMD;
    float ii = gr[dd];
    float ff = gr[DIMD + dd];
    float gg = gr[2 * DIMD + dd];
    float oo = gr[3 * DIMD + dd];
    float cc = sigmoidf_(ff) * g_c[i] + sigmoidf_(ii) * tanhf(gg);
    float hh = sigmoidf_(oo) * tanhf(cc);
    g_c[i] = cc;
    g_h[i] = hh;
    g_xcur[i] = hh + RES_W * g_x0[i];
}

__global__ void logsoftmax_kernel(float* __restrict__ out, int n)
{
    int gw   = (blockIdx.x * blockDim.x + threadIdx.x) >> 5;
    int lane = threadIdx.x & 31;
    if (gw >= n) return;
    float v0 = out[gw * OUTD + lane];
    float v1 = out[gw * OUTD + 32 + lane];
    float mx = fmaxf(v0, v1);
#pragma unroll
    for (int off = 16; off > 0; off >>= 1)
        mx = fmaxf(mx, __shfl_xor_sync(0xFFFFFFFFu, mx, off));
    float se = expf(v0 - mx) + expf(v1 - mx);
#pragma unroll
    for (int off = 16; off > 0; off >>= 1)
        se += __shfl_xor_sync(0xFFFFFFFFu, se, off);
    float lse = mx + logf(se);
    out[gw * OUTD + lane]      = v0 - lse;
    out[gw * OUTD + 32 + lane] = v1 - lse;
}

// ---------------------------------------------------------------------------
// Host side
// ---------------------------------------------------------------------------
static inline int cdiv(int a, int b) { return (a + b - 1) / b; }

extern "C" void kernel_launch(void* const* d_in, const int* in_sizes, int n_in,
                              void* d_out, int out_size)
{
    const float* x_in   = (const float*)d_in[0];
    const int*   ei     = (const int*)  d_in[1];
    const float* lin1_w = (const float*)d_in[2];
    const float* lin1_b = (const float*)d_in[3];
    const float* gat_W  = (const float*)d_in[4];
    const float* att_s  = (const float*)d_in[5];
    const float* att_d  = (const float*)d_in[6];
    const float* gat_b  = (const float*)d_in[7];
    const float* l_Wih  = (const float*)d_in[8];
    const float* l_Whh  = (const float*)d_in[9];
    const float* lin2_w = (const float*)d_in[10];
    const float* lin2_b = (const float*)d_in[11];
    float* out = (float*)d_out;

    const int N = in_sizes[0] / DIMD;
    const int E = in_sizes[1] / 2;
    const int EP = E + N;
    const int* srcp = ei;
    const int* dstp = ei + E;

    float *p_x0, *p_gates, *p_xcur, *p_wt, *p_wcat, *p_htmp, *p_h;
    cudaGetSymbolAddress((void**)&p_x0,    g_x0);
    cudaGetSymbolAddress((void**)&p_gates, g_gates);
    cudaGetSymbolAddress((void**)&p_xcur,  g_xcur);
    cudaGetSymbolAddress((void**)&p_wt,    g_wt);
    cudaGetSymbolAddress((void**)&p_wcat,  g_wcat);
    cudaGetSymbolAddress((void**)&p_htmp,  g_htmp);
    cudaGetSymbolAddress((void**)&p_h,     g_h);
    float* p_xp;
    cudaGetSymbolAddress((void**)&p_xp,    g_xp);

    const int S128 = 2 * (128 + 128) * 36 * 4;   // 73728
    const int S64  = 2 * (128 + 64)  * 36 * 4;   // 55296
    cudaFuncSetAttribute(gemm_mma<128>, cudaFuncAttributeMaxDynamicSharedMemorySize, S128);
    cudaFuncSetAttribute(gemm_mma<64>,  cudaFuncAttributeMaxDynamicSharedMemorySize, S64);

    const int TPB = 256;
    const int ND  = N * DIMD;
    const int gy  = cdiv(N, 128);
    const int nb  = cdiv(N, SCAN_CHUNK);

    // ---- CSR build (once per launch) ----
    csr_zero_kernel<<<cdiv(N, TPB), TPB>>>(N);
    csr_count_kernel<<<cdiv(EP, TPB), TPB>>>(dstp, E, EP);
    scan_block_kernel<<<nb, 256>>>(N);
    scan_bsum_kernel<<<1, 32>>>(nb, N);
    scan_add_kernel<<<cdiv(N, TPB), TPB>>>(N);
    csr_scatter_kernel<<<cdiv(EP, TPB), TPB>>>(srcp, dstp, E, EP);

    // lin1: x0 = x_in @ lin1_w^T + lin1_b
    gemm_mma<128><<<dim3(1, gy), 256, S128>>>(
        x_in, nullptr, nullptr, lin1_w, lin1_b, p_x0, N, DIMD, DIMD);
    init_state_kernel<<<cdiv(ND, TPB), TPB>>>(p_x0, ND);

    for (int L = 0; L < NLAYER; L++) {
        // ---- GAT layer (reads x0) ----
        transpose_kernel<<<cdiv(DIMD * DIMD, TPB), TPB>>>(gat_W + L * DIMD * DIMD);
        gemm_mma<128><<<dim3(1, gy), 256, S128>>>(
            p_x0, nullptr, nullptr, p_wt, nullptr, p_xp, N, DIMD, DIMD);
        alpha_kernel<<<cdiv(N * 32, TPB), TPB>>>(
            (const float4*)(att_s + L * DIMD), (const float4*)(att_d + L * DIMD), N);
        gat_gather_kernel<<<cdiv(N * 32, TPB), TPB>>>(gat_b + L * DIMD, N);

        // ---- LSTM gates: [h_tmp | x_cur | h] @ [Wih|Whh]^T (K=384, Nc=512) ----
        pack_wcat_kernel<<<cdiv(4 * DIMD * 3 * DIMD, TPB), TPB>>>(
            l_Wih + (size_t)L * 4 * DIMD * 2 * DIMD,
            l_Whh + (size_t)L * 4 * DIMD * DIMD);
        gemm_mma<128><<<dim3(4, gy), 256, S128>>>(
            p_htmp, p_xcur, p_h, p_wcat, nullptr, p_gates, N, 4 * DIMD, 3 * DIMD);
        lstm_kernel<<<cdiv(ND, TPB), TPB>>>(N);
    }

    // lin2 + log_softmax
    gemm_mma<64><<<dim3(1, gy), 256, S64>>>(
        p_xcur, nullptr, nullptr, lin2_w, lin2_b, out, N, OUTD, DIMD);
    logsoftmax_kernel<<<cdiv(N * 32, TPB), TPB>>>(out, N);
}

// round 8
// speedup vs baseline: 1.2635x; 1.2635x over previous
#include <cuda_runtime.h>
#include <cuda_fp16.h>
#include <math.h>
#include <float.h>
#include <stdint.h>

// ---------------------------------------------------------------------------
// Problem constants
// ---------------------------------------------------------------------------
#define NN      100000
#define EE_MAX  1700000
#define DIMD    128
#define OUTD    64
#define NLAYER  3
#define NEG_SLOPE 0.2f
#define RES_W     0.5f
#define SCAN_CHUNK 1024

// ---------------------------------------------------------------------------
// Device scratch
// ---------------------------------------------------------------------------
// fp32 state
__device__ __align__(16) float g_x0   [NN * DIMD];
__device__ __align__(16) float g_c    [NN * DIMD];
__device__ __align__(16) float g_gates[NN * 4 * DIMD];
__device__ __align__(16) float g_asrc [NN];
__device__ __align__(16) float g_adst [NN];
// fp16 GEMM operands / activations
__device__ __align__(16) __half g_xinh [NN * DIMD];
__device__ __align__(16) __half g_x0h  [NN * DIMD];
__device__ __align__(16) __half g_xcurh[NN * DIMD];
__device__ __align__(16) __half g_hh   [NN * DIMD];
__device__ __align__(16) __half g_htmph[NN * DIMD];
__device__ __align__(16) __half g_xph  [NN * DIMD];
__device__ __align__(16) __half g_wth  [NLAYER * DIMD * DIMD];
__device__ __align__(16) __half g_wcath[NLAYER * 4 * DIMD * 3 * DIMD];
__device__ __align__(16) __half g_w1h  [DIMD * DIMD];
__device__ __align__(16) __half g_w2h  [OUTD * DIMD];
// CSR scratch
__device__ __align__(16) int   g_deg  [NN];
__device__ __align__(16) int   g_epos [NN];
__device__ __align__(16) int   g_off  [NN + 1];
__device__ __align__(16) int   g_bsum [128];
__device__ __align__(16) int   g_boff [128];
__device__ __align__(16) int   g_esrc [EE_MAX];

// ---------------------------------------------------------------------------
// PTX helpers (sm_80+ ISA; harness targets plain sm_100, no tcgen05)
// ---------------------------------------------------------------------------
__device__ __forceinline__ uint32_t smem_u32(const void* p) {
    uint32_t a;
    asm("{ .reg .u64 t; cvta.to.shared.u64 t, %1; cvt.u32.u64 %0, t; }"
        : "=r"(a) : "l"(p));
    return a;
}

__device__ __forceinline__ void cp16(uint32_t s, const void* g, bool pred) {
    int sz = pred ? 16 : 0;
    asm volatile("cp.async.cg.shared.global [%0], [%1], 16, %2;"
                 :: "r"(s), "l"(g), "r"(sz));
}
__device__ __forceinline__ void cp_commit() {
    asm volatile("cp.async.commit_group;" ::: "memory");
}
template <int N>
__device__ __forceinline__ void cp_wait() {
    asm volatile("cp.async.wait_group %0;" :: "n"(N) : "memory");
}

__device__ __forceinline__ void ldmx4(uint32_t* r, uint32_t addr) {
    asm volatile("ldmatrix.sync.aligned.m8n8.x4.shared.b16 {%0,%1,%2,%3}, [%4];"
                 : "=r"(r[0]), "=r"(r[1]), "=r"(r[2]), "=r"(r[3]) : "r"(addr));
}
__device__ __forceinline__ void mma16816(float* d, const uint32_t* a, const uint32_t* b) {
    asm volatile(
        "mma.sync.aligned.m16n8k16.row.col.f32.f16.f16.f32 "
        "{%0,%1,%2,%3}, {%4,%5,%6,%7}, {%8,%9}, {%0,%1,%2,%3};"
        : "+f"(d[0]), "+f"(d[1]), "+f"(d[2]), "+f"(d[3])
        : "r"(a[0]), "r"(a[1]), "r"(a[2]), "r"(a[3]), "r"(b[0]), "r"(b[1]));
}

// ---------------------------------------------------------------------------
// fp16 mma.sync GEMM:  C[M,Nc] = concat_K(A0|A1|A2)[M,K] @ B[Nc,K]^T (+bias)
// A parts fp16, each 128 halves wide. B fp16, row stride K halves.
// BM=128, BK=32, BN template. 256 thr = 8 warps (4 M x 2 N).
// C (fp32) and Ch (fp16) outputs each optional.
// ---------------------------------------------------------------------------
template <int BN>
__global__ __launch_bounds__(256)
void gemm_h(const __half* __restrict__ a0, const __half* __restrict__ a1,
            const __half* __restrict__ a2, const __half* __restrict__ Bm,
            const float* __restrict__ bias, float* __restrict__ C,
            __half* __restrict__ Ch, int M, int Nc, int K)
{
    constexpr int BM = 128, BK = 32, LDA = BK + 8;   // 40 halves = 80B/row
    constexpr int NTW = BN / 16;
    constexpr int STAGEH = (BM + BN) * LDA;          // halves per stage
    extern __shared__ __half smh[];

    const int tid  = threadIdx.x;
    const int wid  = tid >> 5;
    const int lane = tid & 31;
    const int wm   = wid & 3;
    const int wn   = wid >> 2;
    const int rowBase = blockIdx.y * BM;
    const int colBase = blockIdx.x * BN;
    const __half* aparts[3] = {a0, a1, a2};

    float acc[2][NTW][4];
#pragma unroll
    for (int mt = 0; mt < 2; mt++)
#pragma unroll
        for (int nt = 0; nt < NTW; nt++)
#pragma unroll
            for (int q = 0; q < 4; q++) acc[mt][nt][q] = 0.f;

    const int NCH = K >> 5;

    auto load_chunk = [&](int ck) {
        __half* as = smh + (ck & 1) * STAGEH;
        __half* bs = as + BM * LDA;
        const __half* Ap = aparts[ck >> 2];
        const int kA = (ck & 3) * 32;
        const int k0 = ck * 32;
        for (int i = tid; i < BM * 4; i += 256) {
            int r = i >> 2, c = i & 3;               // c*8 halves = 16B
            int grow = rowBase + r;
            bool ok = grow < M;
            int srow = ok ? grow : (M - 1);          // clamp: address in-bounds
            cp16(smem_u32(as + r * LDA + c * 8),
                 Ap + (size_t)srow * 128 + kA + c * 8, ok);
        }
        for (int i = tid; i < BN * 4; i += 256) {
            int r = i >> 2, c = i & 3;
            cp16(smem_u32(bs + r * LDA + c * 8),
                 Bm + (size_t)(colBase + r) * K + k0 + c * 8, true);
        }
        cp_commit();
    };

    load_chunk(0);
    for (int ck = 0; ck < NCH; ck++) {
        if (ck + 1 < NCH) { load_chunk(ck + 1); cp_wait<1>(); }
        else              { cp_wait<0>(); }
        __syncthreads();

        const __half* as = smh + (ck & 1) * STAGEH;
        const __half* bs = as + BM * LDA;
        // A: x4 -> m0..m3 = {r0-7,k0-7},{r8-15,k0-7},{r0-7,k8-15},{r8-15,k8-15}
        uint32_t aAddr = smem_u32(as) +
            (uint32_t)(((wm * 32 + (lane & 15)) * LDA + ((lane >> 4) << 3)) * 2);
        // B: x4 -> two n8 tiles: {n0-7,k0-7},{n0-7,k8-15},{n8-15,k0-7},{n8-15,k8-15}
        uint32_t bAddr = smem_u32(bs) +
            (uint32_t)(((wn * (BN / 2) + (lane & 7) + ((lane >> 4) << 3)) * LDA
                        + (((lane >> 3) & 1) << 3)) * 2);

#pragma unroll
        for (int ks = 0; ks < 2; ks++) {             // 2 x k16 per chunk
            uint32_t af[2][4];
#pragma unroll
            for (int mt = 0; mt < 2; mt++)
                ldmx4(af[mt], aAddr + (uint32_t)((mt * 16 * LDA + ks * 16) * 2));
            uint32_t bf[NTW][2];
#pragma unroll
            for (int p = 0; p < NTW / 2; p++) {
                uint32_t t[4];
                ldmx4(t, bAddr + (uint32_t)((p * 16 * LDA + ks * 16) * 2));
                bf[2 * p][0]     = t[0];
                bf[2 * p][1]     = t[1];
                bf[2 * p + 1][0] = t[2];
                bf[2 * p + 1][1] = t[3];
            }
#pragma unroll
            for (int mt = 0; mt < 2; mt++)
#pragma unroll
                for (int nt = 0; nt < NTW; nt++)
                    mma16816(acc[mt][nt], af[mt], bf[nt]);
        }
        __syncthreads();
    }

    // epilogue
#pragma unroll
    for (int mt = 0; mt < 2; mt++) {
        int r0 = rowBase + wm * 32 + mt * 16 + (lane >> 2);
#pragma unroll
        for (int nt = 0; nt < NTW; nt++) {
            int col = colBase + wn * (BN / 2) + nt * 8 + (lane & 3) * 2;
            float b0 = 0.f, b1 = 0.f;
            if (bias) { b0 = bias[col]; b1 = bias[col + 1]; }
            float v0 = acc[mt][nt][0] + b0, v1 = acc[mt][nt][1] + b1;
            float v2 = acc[mt][nt][2] + b0, v3 = acc[mt][nt][3] + b1;
            if (r0 < M) {
                if (C)  *(float2*)(C + (size_t)r0 * Nc + col) = make_float2(v0, v1);
                if (Ch) *(__half2*)(Ch + (size_t)r0 * Nc + col) = __floats2half2_rn(v0, v1);
            }
            if (r0 + 8 < M) {
                if (C)  *(float2*)(C + (size_t)(r0 + 8) * Nc + col) = make_float2(v2, v3);
                if (Ch) *(__half2*)(Ch + (size_t)(r0 + 8) * Nc + col) = __floats2half2_rn(v2, v3);
            }
        }
    }
}

// ---------------------------------------------------------------------------
// CSR build (per launch)
// ---------------------------------------------------------------------------
__global__ void csr_zero_kernel(int n)
{
    int i = blockIdx.x * blockDim.x + threadIdx.x;
    if (i < n) { g_deg[i] = 0; g_epos[i] = 0; }
}

__global__ void csr_count_kernel(const int* __restrict__ dst, int E, int EP)
{
    int i = blockIdx.x * blockDim.x + threadIdx.x;
    if (i >= EP) return;
    int d = (i < E) ? dst[i] : (i - E);
    atomicAdd(&g_deg[d], 1);
}

__global__ void scan_block_kernel(int n)
{
    __shared__ int sh[256];
    int t = threadIdx.x;
    int base = blockIdx.x * SCAN_CHUNK;
    int v[4]; int sum = 0;
#pragma unroll
    for (int j = 0; j < 4; j++) {
        int i = base + t * 4 + j;
        v[j] = (i < n) ? g_deg[i] : 0;
        sum += v[j];
    }
    sh[t] = sum;
    __syncthreads();
    for (int off = 1; off < 256; off <<= 1) {
        int y = (t >= off) ? sh[t - off] : 0;
        __syncthreads();
        sh[t] += y;
        __syncthreads();
    }
    int excl = sh[t] - sum;
#pragma unroll
    for (int j = 0; j < 4; j++) {
        int i = base + t * 4 + j;
        if (i < n) g_off[i] = excl;
        excl += v[j];
    }
    if (t == 255) g_bsum[blockIdx.x] = sh[255];
}

__global__ void scan_bsum_kernel(int nb, int n)
{
    if (threadIdx.x == 0 && blockIdx.x == 0) {
        int run = 0;
        for (int b = 0; b < nb; b++) {
            int t = g_bsum[b];
            g_boff[b] = run;
            run += t;
        }
        g_off[n] = run;
    }
}

__global__ void scan_add_kernel(int n)
{
    int i = blockIdx.x * blockDim.x + threadIdx.x;
    if (i < n) g_off[i] += g_boff[i / SCAN_CHUNK];
}

__global__ void csr_scatter_kernel(const int* __restrict__ src,
                                   const int* __restrict__ dst, int E, int EP)
{
    int i = blockIdx.x * blockDim.x + threadIdx.x;
    if (i >= EP) return;
    int s = (i < E) ? src[i] : (i - E);
    int d = (i < E) ? dst[i] : (i - E);
    int pos = g_off[d] + atomicAdd(&g_epos[d], 1);
    g_esrc[pos] = s;
}

// ---------------------------------------------------------------------------
// Converts / packs
// ---------------------------------------------------------------------------
__global__ void f2h_kernel(const float* __restrict__ in, __half* __restrict__ out,
                           int n4)
{
    int i = blockIdx.x * blockDim.x + threadIdx.x;
    if (i >= n4) return;
    float4 v = ((const float4*)in)[i];
    __half2 a = __floats2half2_rn(v.x, v.y);
    __half2 b = __floats2half2_rn(v.z, v.w);
    uint2 u;
    *(__half2*)&u.x = a;
    *(__half2*)&u.y = b;
    ((uint2*)out)[i] = u;
}

// all 3 layers' W transposed -> fp16
__global__ void transpose3_kernel(const float* __restrict__ W)
{
    int i = blockIdx.x * blockDim.x + threadIdx.x;
    if (i >= NLAYER * DIMD * DIMD) return;
    int l  = i / (DIMD * DIMD);
    int rc = i - l * (DIMD * DIMD);
    int r = rc >> 7, c = rc & 127;
    g_wth[i] = __float2half_rn(W[l * DIMD * DIMD + c * DIMD + r]);
}

// all 3 layers' [Wih|Whh] packed -> fp16
__global__ void pack_wcat3_kernel(const float* __restrict__ Wih,
                                  const float* __restrict__ Whh)
{
    const int per = 4 * DIMD * 3 * DIMD;
    int i = blockIdx.x * blockDim.x + threadIdx.x;
    if (i >= NLAYER * per) return;
    int l = i / per;
    int j = i - l * per;
    int r = j / (3 * DIMD);
    int c = j - r * (3 * DIMD);
    float v = (c < 2 * DIMD)
        ? Wih[(size_t)l * 4 * DIMD * 2 * DIMD + r * 2 * DIMD + c]
        : Whh[(size_t)l * 4 * DIMD * DIMD + r * DIMD + (c - 2 * DIMD)];
    g_wcath[i] = __float2half_rn(v);
}

// ---------------------------------------------------------------------------
// Per-node kernels
// ---------------------------------------------------------------------------
__global__ void init_state_kernel(int count)
{
    int i = blockIdx.x * blockDim.x + threadIdx.x;
    if (i >= count) return;
    g_xcurh[i] = g_x0h[i];
    g_hh[i] = __float2half(0.f);
    g_c[i] = 0.f;
}

__global__ void alpha_kernel(const float4* __restrict__ as4,
                             const float4* __restrict__ ad4, int n)
{
    int gw   = (blockIdx.x * blockDim.x + threadIdx.x) >> 5;
    int lane = threadIdx.x & 31;
    if (gw >= n) return;
    uint2 u = ((const uint2*)g_xph)[gw * 32 + lane];
    float2 f0 = __half22float2(*(__half2*)&u.x);
    float2 f1 = __half22float2(*(__half2*)&u.y);
    float4 s4 = as4[lane];
    float4 d4 = ad4[lane];
    float ds = f0.x * s4.x + f0.y * s4.y + f1.x * s4.z + f1.y * s4.w;
    float dd = f0.x * d4.x + f0.y * d4.y + f1.x * d4.z + f1.y * d4.w;
#pragma unroll
    for (int off = 16; off > 0; off >>= 1) {
        ds += __shfl_xor_sync(0xFFFFFFFFu, ds, off);
        dd += __shfl_xor_sync(0xFFFFFFFFu, dd, off);
    }
    if (lane == 0) { g_asrc[gw] = ds; g_adst[gw] = dd; }
}

__device__ __forceinline__ float leaky(float e)
{
    return e > 0.f ? e : NEG_SLOPE * e;
}

// Fused GAT aggregation: warp per dst node, CSR gather, softmax, tanh -> fp16 htmp
__global__ void gat_gather_kernel(const float* __restrict__ gat_b, int n)
{
    int gw   = (blockIdx.x * blockDim.x + threadIdx.x) >> 5;
    int lane = threadIdx.x & 31;
    if (gw >= n) return;

    const int o0 = g_off[gw];
    const int o1 = g_off[gw + 1];
    const float ad = g_adst[gw];

    float m = -FLT_MAX;
    for (int e = o0 + lane; e < o1; e += 32) {
        int s = g_esrc[e];
        m = fmaxf(m, leaky(g_asrc[s] + ad));
    }
#pragma unroll
    for (int off = 16; off > 0; off >>= 1)
        m = fmaxf(m, __shfl_xor_sync(0xFFFFFFFFu, m, off));

    float4 acc = make_float4(0.f, 0.f, 0.f, 0.f);
    float den = 0.f;
    for (int b = o0; b < o1; b += 32) {
        int e = b + lane;
        int s = 0; float ex = 0.f;
        if (e < o1) {
            s = g_esrc[e];
            ex = expf(leaky(g_asrc[s] + ad) - m);
        }
        den += ex;
        int cnt = min(32, o1 - b);
        for (int j = 0; j < cnt; j++) {
            float exj = __shfl_sync(0xFFFFFFFFu, ex, j);
            int   sj  = __shfl_sync(0xFFFFFFFFu, s, j);
            uint2 u = ((const uint2*)g_xph)[sj * 32 + lane];
            float2 fa = __half22float2(*(__half2*)&u.x);
            float2 fb = __half22float2(*(__half2*)&u.y);
            acc.x += exj * fa.x;
            acc.y += exj * fa.y;
            acc.z += exj * fb.x;
            acc.w += exj * fb.y;
        }
    }
#pragma unroll
    for (int off = 16; off > 0; off >>= 1)
        den += __shfl_xor_sync(0xFFFFFFFFu, den, off);

    float inv = 1.f / (den + 1e-16f);
    float4 bv = ((const float4*)gat_b)[lane];
    uint2 uo;
    *(__half2*)&uo.x = __floats2half2_rn(tanhf(acc.x * inv + bv.x),
                                         tanhf(acc.y * inv + bv.y));
    *(__half2*)&uo.y = __floats2half2_rn(tanhf(acc.z * inv + bv.z),
                                         tanhf(acc.w * inv + bv.w));
    ((uint2*)g_htmph)[gw * 32 + lane] = uo;
}

__device__ __forceinline__ float sigmoidf_(float x)
{
    return 1.f / (1.f + expf(-x));
}

__global__ void lstm_kernel(int n)
{
    int i = blockIdx.x * blockDim.x + threadIdx.x;
    if (i >= n * DIMD) return;
    int node = i >> 7;
    int dd   = i & 127;
    const float* gr = g_gates + (size_t)node * 4 * DIMD;
    float ii = gr[dd];
    float ff = gr[DIMD + dd];
    float gg = gr[2 * DIMD + dd];
    float oo = gr[3 * DIMD + dd];
    float cc = sigmoidf_(ff) * g_c[i] + sigmoidf_(ii) * tanhf(gg);
    float hh = sigmoidf_(oo) * tanhf(cc);
    g_c[i] = cc;
    g_hh[i] = __float2half_rn(hh);
    g_xcurh[i] = __float2half_rn(hh + RES_W * g_x0[i]);
}

__global__ void logsoftmax_kernel(float* __restrict__ out, int n)
{
    int gw   = (blockIdx.x * blockDim.x + threadIdx.x) >> 5;
    int lane = threadIdx.x & 31;
    if (gw >= n) return;
    float v0 = out[gw * OUTD + lane];
    float v1 = out[gw * OUTD + 32 + lane];
    float mx = fmaxf(v0, v1);
#pragma unroll
    for (int off = 16; off > 0; off >>= 1)
        mx = fmaxf(mx, __shfl_xor_sync(0xFFFFFFFFu, mx, off));
    float se = expf(v0 - mx) + expf(v1 - mx);
#pragma unroll
    for (int off = 16; off > 0; off >>= 1)
        se += __shfl_xor_sync(0xFFFFFFFFu, se, off);
    float lse = mx + logf(se);
    out[gw * OUTD + lane]      = v0 - lse;
    out[gw * OUTD + 32 + lane] = v1 - lse;
}

// ---------------------------------------------------------------------------
// Host side
// ---------------------------------------------------------------------------
static inline int cdiv(int a, int b) { return (a + b - 1) / b; }

extern "C" void kernel_launch(void* const* d_in, const int* in_sizes, int n_in,
                              void* d_out, int out_size)
{
    const float* x_in   = (const float*)d_in[0];
    const int*   ei     = (const int*)  d_in[1];
    const float* lin1_w = (const float*)d_in[2];
    const float* lin1_b = (const float*)d_in[3];
    const float* gat_W  = (const float*)d_in[4];
    const float* att_s  = (const float*)d_in[5];
    const float* att_d  = (const float*)d_in[6];
    const float* gat_b  = (const float*)d_in[7];
    const float* l_Wih  = (const float*)d_in[8];
    const float* l_Whh  = (const float*)d_in[9];
    const float* lin2_w = (const float*)d_in[10];
    const float* lin2_b = (const float*)d_in[11];
    float* out = (float*)d_out;

    const int N = in_sizes[0] / DIMD;
    const int E = in_sizes[1] / 2;
    const int EP = E + N;
    const int* srcp = ei;
    const int* dstp = ei + E;

    float *p_x0, *p_gates;
    cudaGetSymbolAddress((void**)&p_x0,    g_x0);
    cudaGetSymbolAddress((void**)&p_gates, g_gates);
    __half *p_xinh, *p_x0h, *p_xcurh, *p_hh, *p_htmph, *p_xph, *p_wth, *p_wcath,
           *p_w1h, *p_w2h;
    cudaGetSymbolAddress((void**)&p_xinh,  g_xinh);
    cudaGetSymbolAddress((void**)&p_x0h,   g_x0h);
    cudaGetSymbolAddress((void**)&p_xcurh, g_xcurh);
    cudaGetSymbolAddress((void**)&p_hh,    g_hh);
    cudaGetSymbolAddress((void**)&p_htmph, g_htmph);
    cudaGetSymbolAddress((void**)&p_xph,   g_xph);
    cudaGetSymbolAddress((void**)&p_wth,   g_wth);
    cudaGetSymbolAddress((void**)&p_wcath, g_wcath);
    cudaGetSymbolAddress((void**)&p_w1h,   g_w1h);
    cudaGetSymbolAddress((void**)&p_w2h,   g_w2h);

    const int S128 = 2 * (128 + 128) * 40 * 2;   // 40960 bytes
    const int S64  = 2 * (128 + 64)  * 40 * 2;   // 30720 bytes
    cudaFuncSetAttribute(gemm_h<128>, cudaFuncAttributeMaxDynamicSharedMemorySize, S128);
    cudaFuncSetAttribute(gemm_h<64>,  cudaFuncAttributeMaxDynamicSharedMemorySize, S64);

    const int TPB = 256;
    const int ND  = N * DIMD;
    const int gy  = cdiv(N, 128);
    const int nb  = cdiv(N, SCAN_CHUNK);
    const int WCAT = 4 * DIMD * 3 * DIMD;

    // ---- converts / packs (once per launch) ----
    f2h_kernel<<<cdiv(ND / 4, TPB), TPB>>>(x_in, p_xinh, ND / 4);
    f2h_kernel<<<cdiv(DIMD * DIMD / 4, TPB), TPB>>>(lin1_w, p_w1h, DIMD * DIMD / 4);
    f2h_kernel<<<cdiv(OUTD * DIMD / 4, TPB), TPB>>>(lin2_w, p_w2h, OUTD * DIMD / 4);
    transpose3_kernel<<<cdiv(NLAYER * DIMD * DIMD, TPB), TPB>>>(gat_W);
    pack_wcat3_kernel<<<cdiv(NLAYER * WCAT, TPB), TPB>>>(l_Wih, l_Whh);

    // ---- CSR build ----
    csr_zero_kernel<<<cdiv(N, TPB), TPB>>>(N);
    csr_count_kernel<<<cdiv(EP, TPB), TPB>>>(dstp, E, EP);
    scan_block_kernel<<<nb, 256>>>(N);
    scan_bsum_kernel<<<1, 32>>>(nb, N);
    scan_add_kernel<<<cdiv(N, TPB), TPB>>>(N);
    csr_scatter_kernel<<<cdiv(EP, TPB), TPB>>>(srcp, dstp, E, EP);

    // lin1: x0 = x_in @ lin1_w^T + lin1_b  (fp32 + fp16 outputs)
    gemm_h<128><<<dim3(1, gy), 256, S128>>>(
        p_xinh, nullptr, nullptr, p_w1h, lin1_b, p_x0, p_x0h, N, DIMD, DIMD);
    init_state_kernel<<<cdiv(ND, TPB), TPB>>>(ND);

    for (int L = 0; L < NLAYER; L++) {
        // ---- GAT layer (reads x0h) ----
        gemm_h<128><<<dim3(1, gy), 256, S128>>>(
            p_x0h, nullptr, nullptr, p_wth + (size_t)L * DIMD * DIMD,
            nullptr, nullptr, p_xph, N, DIMD, DIMD);
        alpha_kernel<<<cdiv(N * 32, TPB), TPB>>>(
            (const float4*)(att_s + L * DIMD), (const float4*)(att_d + L * DIMD), N);
        gat_gather_kernel<<<cdiv(N * 32, TPB), TPB>>>(gat_b + L * DIMD, N);

        // ---- LSTM gates: [htmp | xcur | h] @ [Wih|Whh]^T (K=384, Nc=512) ----
        gemm_h<128><<<dim3(4, gy), 256, S128>>>(
            p_htmph, p_xcurh, p_hh, p_wcath + (size_t)L * WCAT,
            nullptr, p_gates, nullptr, N, 4 * DIMD, 3 * DIMD);
        lstm_kernel<<<cdiv(ND, TPB), TPB>>>(N);
    }

    // lin2 + log_softmax
    gemm_h<64><<<dim3(1, gy), 256, S64>>>(
        p_xcurh, nullptr, nullptr, p_w2h, lin2_b, out, nullptr, N, OUTD, DIMD);
    logsoftmax_kernel<<<cdiv(N * 32, TPB), TPB>>>(out, N);
}